// round 5
// baseline (speedup 1.0000x reference)
#include <cuda_runtime.h>

#define NQ    12
#define DIMN  4096
#define NGEN  2

// ---------------- complex helpers ----------------
__device__ __forceinline__ float2 cmul(float2 a, float2 b){
    return make_float2(fmaf(a.x, b.x, -(a.y * b.y)), fmaf(a.x, b.y, a.y * b.x));
}
__device__ __forceinline__ float2 cmac(float2 acc, float2 g, float2 a){
    acc.x = fmaf(g.x, a.x, fmaf(-g.y, a.y, acc.x));
    acc.y = fmaf(g.x, a.y, fmaf(g.y, a.x, acc.y));
    return acc;
}
__device__ __forceinline__ float2 row4(const float2* g, float2 a0, float2 a1, float2 a2, float2 a3){
    float2 n = cmul(g[0], a0);
    n = cmac(n, g[1], a1);
    n = cmac(n, g[2], a2);
    n = cmac(n, g[3], a3);
    return n;
}

// CNOT ring permutation: s_after[i] = s_before[perm_src(i)]
// ops in time order: CNOT(0,1)..CNOT(10,11), CNOT(11,0); wire y <-> bit (11-y).
__device__ __forceinline__ int perm_src(int i){
    int j = i ^ ((i & 1) << 11);          // CNOT(11,0): ctrl bit0 -> flip bit11 (applied innermost)
#pragma unroll
    for (int cb = 1; cb <= 11; ++cb)       // CNOT(y,y+1): ctrl bit cb=11-y -> flip bit cb-1
        j ^= ((j >> cb) & 1) << (cb - 1);
    return j;
}

// bank-conflict swizzle for the state array
__device__ __forceinline__ int swz(int i){ return i ^ ((i >> 4) & 15); }

// ---------------- quantum circuit kernel ----------------
// grid: (4096 batch, 2 gen), block: 256 threads. State (4096 complex) in SMEM.
__global__ void __launch_bounds__(256)
qsim_kernel(const float* __restrict__ x,
            const float* __restrict__ qp,
            float* __restrict__ out)
{
    __shared__ float2 st[4096];        // statevector (swizzled layout)
    __shared__ float2 Mg[2][12][4];    // fused RY*RX*RZ for layers 1,2 (row-major 2x2)
    __shared__ float2 G4[2][6][16];    // fused 4x4 two-qubit gates
    __shared__ float2 v[12][2];        // layer-0 column vectors (per-sample)
    __shared__ float2 lowtab[16];      // product over wires 8..11
    __shared__ float2 hitab[256];      // product over wires 0..7

    const int tid = threadIdx.x;
    const int b   = blockIdx.x;
    const int g   = blockIdx.y;
    const float* w = qp + g * (3 * NQ * 3);

    // ---- phase 1: fused single-qubit gates (threads 0..35) ----
    if (tid < 36) {
        const int l = tid / 12, q = tid % 12;
        const float* wp = w + l * 36 + q * 3;
        float s1, c1, s2, c2, s3, c3;
        sincosf(0.5f * wp[0], &s1, &c1);
        sincosf(0.5f * wp[1], &s2, &c2);
        sincosf(0.5f * wp[2], &s3, &c3);
        // A = RX * RZ
        float2 A00 = make_float2( c2 * c1, -c2 * s1);
        float2 A01 = make_float2( s2 * s1, -s2 * c1);
        float2 A10 = make_float2(-s2 * s1, -s2 * c1);
        float2 A11 = make_float2( c2 * c1,  c2 * s1);
        // M = RY * A
        float2 M00 = make_float2(c3*A00.x - s3*A10.x, c3*A00.y - s3*A10.y);
        float2 M01 = make_float2(c3*A01.x - s3*A11.x, c3*A01.y - s3*A11.y);
        float2 M10 = make_float2(s3*A00.x + c3*A10.x, s3*A00.y + c3*A10.y);
        float2 M11 = make_float2(s3*A01.x + c3*A11.x, s3*A01.y + c3*A11.y);
        if (l == 0) {
            float sx, cx;
            sincosf(0.5f * x[b * NQ + q], &sx, &cx);
            v[q][0] = make_float2(M00.x*cx + M01.x*sx, M00.y*cx + M01.y*sx);
            v[q][1] = make_float2(M10.x*cx + M11.x*sx, M10.y*cx + M11.y*sx);
        } else {
            Mg[l-1][q][0] = M00; Mg[l-1][q][1] = M01;
            Mg[l-1][q][2] = M10; Mg[l-1][q][3] = M11;
        }
    }
    __syncthreads();

    // ---- phase 2: 4x4 kron gates, low/high product tables ----
    if (tid < 192) {
        const int l = tid / 96, u = tid % 96, pr = u / 16, e = u % 16;
        const int r = e >> 2, c = e & 3;
        G4[l][pr][e] = cmul(Mg[l][2*pr    ][(r >> 1) * 2 + (c >> 1)],
                            Mg[l][2*pr + 1][(r &  1) * 2 + (c &  1)]);
    } else if (tid < 208) {
        const int idx = tid - 192;
        lowtab[idx] = cmul(cmul(v[8][(idx >> 3) & 1], v[ 9][(idx >> 2) & 1]),
                           cmul(v[10][(idx >> 1) & 1], v[11][ idx       & 1]));
    }
    {
        float2 hv = v[0][(tid >> 7) & 1];
#pragma unroll
        for (int y = 1; y < 8; ++y)
            hv = cmul(hv, v[y][(tid >> (7 - y)) & 1]);
        hitab[tid] = hv;
    }
    __syncthreads();

    // ---- init: product state with layer-0 CNOT-ring perm fused in ----
#pragma unroll
    for (int r = 0; r < 16; ++r) {
        const int i = tid + 256 * r;
        const int j = perm_src(i);
        st[swz(i)] = cmul(hitab[j >> 4], lowtab[j & 15]);
    }
    __syncthreads();

    // ---- layers 1 and 2 ----
#pragma unroll
    for (int l = 0; l < 2; ++l) {
        // strided 4x4 passes: wire pairs (0,1)(2,3)(4,5)(6,7) -> k = 10,8,6,4
#pragma unroll
        for (int P = 0; P < 4; ++P) {
            const int k = 10 - 2 * P;
            const int s = 1 << k;
            float2 gm[16];
#pragma unroll
            for (int e = 0; e < 16; ++e) gm[e] = G4[l][P][e];
#pragma unroll
            for (int rr = 0; rr < 4; ++rr) {
                const int p  = tid + 256 * rr;
                const int i0 = ((p >> k) << (k + 2)) | (p & (s - 1));
                float2 a0 = st[swz(i0)];
                float2 a1 = st[swz(i0 + s)];
                float2 a2 = st[swz(i0 + 2 * s)];
                float2 a3 = st[swz(i0 + 3 * s)];
                float2 n0 = row4(gm +  0, a0, a1, a2, a3);
                float2 n1 = row4(gm +  4, a0, a1, a2, a3);
                float2 n2 = row4(gm +  8, a0, a1, a2, a3);
                float2 n3 = row4(gm + 12, a0, a1, a2, a3);
                st[swz(i0)]         = n0;
                st[swz(i0 + s)]     = n1;
                st[swz(i0 + 2 * s)] = n2;
                st[swz(i0 + 3 * s)] = n3;
            }
            __syncthreads();
        }

        // local pass: wires (8,9) and (10,11) = index bits (3,2) and (1,0),
        // one 16-amp register block per thread, one SMEM round-trip for 2 gates
        {
            float2 a[16];
            const int base = tid << 4;
            const int sx4  = tid & 15;
#pragma unroll
            for (int c = 0; c < 16; ++c) a[c] = st[base | (c ^ sx4)];

            {   // gate on bits (3,2)  (pair P=4)
                float2 gm[16];
#pragma unroll
                for (int e = 0; e < 16; ++e) gm[e] = G4[l][4][e];
#pragma unroll
                for (int lo = 0; lo < 4; ++lo) {
                    float2 b0 = a[lo], b1 = a[4 | lo], b2 = a[8 | lo], b3 = a[12 | lo];
                    a[lo]      = row4(gm +  0, b0, b1, b2, b3);
                    a[4 | lo]  = row4(gm +  4, b0, b1, b2, b3);
                    a[8 | lo]  = row4(gm +  8, b0, b1, b2, b3);
                    a[12 | lo] = row4(gm + 12, b0, b1, b2, b3);
                }
            }
            {   // gate on bits (1,0)  (pair P=5)
                float2 gm[16];
#pragma unroll
                for (int e = 0; e < 16; ++e) gm[e] = G4[l][5][e];
#pragma unroll
                for (int hi = 0; hi < 4; ++hi) {
                    float2 b0 = a[hi*4], b1 = a[hi*4+1], b2 = a[hi*4+2], b3 = a[hi*4+3];
                    a[hi*4+0] = row4(gm +  0, b0, b1, b2, b3);
                    a[hi*4+1] = row4(gm +  4, b0, b1, b2, b3);
                    a[hi*4+2] = row4(gm +  8, b0, b1, b2, b3);
                    a[hi*4+3] = row4(gm + 12, b0, b1, b2, b3);
                }
            }
#pragma unroll
            for (int c = 0; c < 16; ++c) st[base | (c ^ sx4)] = a[c];
        }
        __syncthreads();

        if (l == 0) {   // explicit CNOT-ring perm between layer 1 and layer 2
            float2 tmp[16];
#pragma unroll
            for (int r = 0; r < 16; ++r)
                tmp[r] = st[swz(perm_src(tid + 256 * r))];
            __syncthreads();
#pragma unroll
            for (int r = 0; r < 16; ++r)
                st[swz(tid + 256 * r)] = tmp[r];
            __syncthreads();
        }
    }

    // ---- probabilities, with layer-2 CNOT-ring perm fused into the read ----
    float* orow = out + (size_t)b * (NGEN * DIMN) + (size_t)g * DIMN;
#pragma unroll
    for (int r = 0; r < 16; ++r) {
        const int i = tid + 256 * r;
        float2 a = st[swz(perm_src(i))];
        orow[i] = fmaf(a.x, a.x, a.y * a.y);
    }
}

// ---------------- linear layer: (x @ W^T + b) * 5 ----------------
__global__ void __launch_bounds__(256)
linear_kernel(const float* __restrict__ x,
              const float* __restrict__ lw,
              const float* __restrict__ lb,
              float* __restrict__ out)
{
    __shared__ float xr[NQ];
    const int b = blockIdx.x;
    const int tid = threadIdx.x;
    if (tid < NQ) xr[tid] = x[b * NQ + tid];
    __syncthreads();
    float xl[NQ];
#pragma unroll
    for (int j = 0; j < NQ; ++j) xl[j] = xr[j];

    float* orow = out + (size_t)b * DIMN;
    for (int d = tid; d < DIMN; d += 256) {
        const float4* wr = reinterpret_cast<const float4*>(lw + (size_t)d * NQ);
        float4 w0 = wr[0], w1 = wr[1], w2 = wr[2];
        float acc = lb[d];
        acc = fmaf(xl[0],  w0.x, acc); acc = fmaf(xl[1],  w0.y, acc);
        acc = fmaf(xl[2],  w0.z, acc); acc = fmaf(xl[3],  w0.w, acc);
        acc = fmaf(xl[4],  w1.x, acc); acc = fmaf(xl[5],  w1.y, acc);
        acc = fmaf(xl[6],  w1.z, acc); acc = fmaf(xl[7],  w1.w, acc);
        acc = fmaf(xl[8],  w2.x, acc); acc = fmaf(xl[9],  w2.y, acc);
        acc = fmaf(xl[10], w2.z, acc); acc = fmaf(xl[11], w2.w, acc);
        orow[d] = acc * 5.0f;
    }
}

extern "C" void kernel_launch(void* const* d_in, const int* in_sizes, int n_in,
                              void* d_out, int out_size)
{
    const float* x  = (const float*)d_in[0];   // (4096, 12)
    const float* qp = (const float*)d_in[1];   // (2, 108)
    const float* lw = (const float*)d_in[2];   // (4096, 12)
    const float* lb = (const float*)d_in[3];   // (4096,)
    float* out = (float*)d_out;                // probs (4096,8192) then converted_x (4096,4096)

    dim3 grid(4096, NGEN);
    qsim_kernel<<<grid, 256>>>(x, qp, out);
    linear_kernel<<<4096, 256>>>(x, lw, lb, out + (size_t)4096 * (NGEN * DIMN));
}

// round 6
// speedup vs baseline: 1.2590x; 1.2590x over previous
#include <cuda_runtime.h>

#define NQ    12
#define DIMN  4096
#define NGEN  2

typedef unsigned long long u64;

// ---------------- packed f32x2 helpers ----------------
__device__ __forceinline__ u64 pk(float lo, float hi){
    u64 r; asm("mov.b64 %0, {%1, %2};" : "=l"(r) : "f"(lo), "f"(hi)); return r;
}
__device__ __forceinline__ void upk(u64 v, float& lo, float& hi){
    asm("mov.b64 {%0, %1}, %2;" : "=f"(lo), "=f"(hi) : "l"(v));
}
__device__ __forceinline__ u64 f2mul(u64 a, u64 b){
    u64 d; asm("mul.rn.f32x2 %0, %1, %2;" : "=l"(d) : "l"(a), "l"(b)); return d;
}
__device__ __forceinline__ u64 f2fma(u64 a, u64 b, u64 c){
    u64 d; asm("fma.rn.f32x2 %0, %1, %2, %3;" : "=l"(d) : "l"(a), "l"(b), "l"(c)); return d;
}
__device__ __forceinline__ u64 swapp(u64 v){          // (x,y) -> (y,x)
    float lo, hi; upk(v, lo, hi); return pk(hi, lo);
}

// scalar complex helpers (setup phases only)
__device__ __forceinline__ float2 cmul(float2 a, float2 b){
    return make_float2(fmaf(a.x, b.x, -(a.y * b.y)), fmaf(a.x, b.y, a.y * b.x));
}

// CNOT ring permutation, closed form of the gate sequence
// CNOT(0,1)..CNOT(10,11), CNOT(11,0); wire y <-> bit (11-y).
// j0 = i ^ ((i&1)<<11); out bit b = j0_b ^ j0_{b+1}  =>  out = j0 ^ (j0>>1)
__device__ __forceinline__ int perm_src(int i){
    int j0 = i ^ ((i & 1) << 11);
    return j0 ^ (j0 >> 1);
}

// bank-conflict swizzle for the state array
__device__ __forceinline__ int swz(int i){ return i ^ ((i >> 4) & 15); }

// packed row of a 4x4 complex gate: n = sum_k P[k](.)A[k] + Q[k](.)S[k]
__device__ __forceinline__ u64 row4p(const u64* __restrict__ P, const u64* __restrict__ Q,
                                     const u64* __restrict__ A, const u64* __restrict__ S){
    u64 n = f2mul(P[0], A[0]);
    n = f2fma(Q[0], S[0], n);
    n = f2fma(P[1], A[1], n);
    n = f2fma(Q[1], S[1], n);
    n = f2fma(P[2], A[2], n);
    n = f2fma(Q[2], S[2], n);
    n = f2fma(P[3], A[3], n);
    n = f2fma(Q[3], S[3], n);
    return n;
}

// ---------------- quantum circuit kernel ----------------
// grid: (4096 batch, 2 gen), block: 256 threads. State (4096 complex) in SMEM.
__global__ void __launch_bounds__(256, 2)
qsim_kernel(const float* __restrict__ x,
            const float* __restrict__ qp,
            float* __restrict__ out)
{
    __shared__ float2 st[4096];        // statevector (swizzled layout)
    __shared__ float2 Mg[2][12][4];    // fused RY*RX*RZ for layers 1,2
    __shared__ u64 G4P[2][6][16];      // (gx,gx) pairs of 4x4 gates
    __shared__ u64 G4Q[2][6][16];      // (-gy,gy) pairs of 4x4 gates
    __shared__ float2 v[12][2];        // layer-0 column vectors (per-sample)
    __shared__ float2 lowtab[16];      // product over wires 8..11
    __shared__ float2 hitab[256];      // product over wires 0..7

    const int tid = threadIdx.x;
    const int b   = blockIdx.x;
    const int g   = blockIdx.y;
    const float* w = qp + g * (3 * NQ * 3);

    // ---- phase 1: fused single-qubit gates (threads 0..35) ----
    if (tid < 36) {
        const int l = tid / 12, q = tid % 12;
        const float* wp = w + l * 36 + q * 3;
        float s1, c1, s2, c2, s3, c3;
        sincosf(0.5f * wp[0], &s1, &c1);
        sincosf(0.5f * wp[1], &s2, &c2);
        sincosf(0.5f * wp[2], &s3, &c3);
        float2 A00 = make_float2( c2 * c1, -c2 * s1);
        float2 A01 = make_float2( s2 * s1, -s2 * c1);
        float2 A10 = make_float2(-s2 * s1, -s2 * c1);
        float2 A11 = make_float2( c2 * c1,  c2 * s1);
        float2 M00 = make_float2(c3*A00.x - s3*A10.x, c3*A00.y - s3*A10.y);
        float2 M01 = make_float2(c3*A01.x - s3*A11.x, c3*A01.y - s3*A11.y);
        float2 M10 = make_float2(s3*A00.x + c3*A10.x, s3*A00.y + c3*A10.y);
        float2 M11 = make_float2(s3*A01.x + c3*A11.x, s3*A01.y + c3*A11.y);
        if (l == 0) {
            float sx, cx;
            sincosf(0.5f * x[b * NQ + q], &sx, &cx);
            v[q][0] = make_float2(M00.x*cx + M01.x*sx, M00.y*cx + M01.y*sx);
            v[q][1] = make_float2(M10.x*cx + M11.x*sx, M10.y*cx + M11.y*sx);
        } else {
            Mg[l-1][q][0] = M00; Mg[l-1][q][1] = M01;
            Mg[l-1][q][2] = M10; Mg[l-1][q][3] = M11;
        }
    }
    __syncthreads();

    // ---- phase 2: packed 4x4 kron gates, low/high product tables ----
    if (tid < 192) {
        const int l = tid / 96, u = tid % 96, pr = u / 16, e = u % 16;
        const int r = e >> 2, c = e & 3;
        float2 gm = cmul(Mg[l][2*pr    ][(r >> 1) * 2 + (c >> 1)],
                         Mg[l][2*pr + 1][(r &  1) * 2 + (c &  1)]);
        G4P[l][pr][e] = pk(gm.x, gm.x);
        G4Q[l][pr][e] = pk(-gm.y, gm.y);
    } else if (tid < 208) {
        const int idx = tid - 192;
        lowtab[idx] = cmul(cmul(v[8][(idx >> 3) & 1], v[ 9][(idx >> 2) & 1]),
                           cmul(v[10][(idx >> 1) & 1], v[11][ idx       & 1]));
    }
    {
        float2 hv = v[0][(tid >> 7) & 1];
#pragma unroll
        for (int y = 1; y < 8; ++y)
            hv = cmul(hv, v[y][(tid >> (7 - y)) & 1]);
        hitab[tid] = hv;
    }
    __syncthreads();

    // ---- init: product state with layer-0 CNOT-ring perm fused in ----
#pragma unroll
    for (int r = 0; r < 16; ++r) {
        const int i = tid + 256 * r;
        const int j = perm_src(i);
        st[swz(i)] = cmul(hitab[j >> 4], lowtab[j & 15]);
    }
    __syncthreads();

    // ---- layers 1 and 2 (packed f32x2 math) ----
#pragma unroll
    for (int l = 0; l < 2; ++l) {
        // strided 4x4 passes: wire pairs (0,1)(2,3)(4,5)(6,7) -> k = 10,8,6,4
#pragma unroll
        for (int P = 0; P < 4; ++P) {
            const int k = 10 - 2 * P;
            const int s = 1 << k;
            u64 Pg[16], Qg[16];
#pragma unroll
            for (int e = 0; e < 16; ++e){ Pg[e] = G4P[l][P][e]; Qg[e] = G4Q[l][P][e]; }
#pragma unroll
            for (int rr = 0; rr < 4; ++rr) {
                const int p  = tid + 256 * rr;
                const int i0 = ((p >> k) << (k + 2)) | (p & (s - 1));
                u64 A[4], S[4];
#pragma unroll
                for (int q = 0; q < 4; ++q){
                    A[q] = *reinterpret_cast<const u64*>(&st[swz(i0 + q * s)]);
                    S[q] = swapp(A[q]);
                }
                u64 n0 = row4p(Pg +  0, Qg +  0, A, S);
                u64 n1 = row4p(Pg +  4, Qg +  4, A, S);
                u64 n2 = row4p(Pg +  8, Qg +  8, A, S);
                u64 n3 = row4p(Pg + 12, Qg + 12, A, S);
                *reinterpret_cast<u64*>(&st[swz(i0)])         = n0;
                *reinterpret_cast<u64*>(&st[swz(i0 + s)])     = n1;
                *reinterpret_cast<u64*>(&st[swz(i0 + 2*s)])   = n2;
                *reinterpret_cast<u64*>(&st[swz(i0 + 3*s)])   = n3;
            }
            __syncthreads();
        }

        // local pass: bits (3,2) then (1,0); 16 amps per thread, 1 SMEM round trip
        {
            u64 a[16];
            const int base = tid << 4;
            const int sx4  = tid & 15;
#pragma unroll
            for (int c = 0; c < 16; ++c)
                a[c] = *reinterpret_cast<const u64*>(&st[base | (c ^ sx4)]);

            {   // gate on bits (3,2)  (pair 4)
                u64 Pg[16], Qg[16];
#pragma unroll
                for (int e = 0; e < 16; ++e){ Pg[e] = G4P[l][4][e]; Qg[e] = G4Q[l][4][e]; }
#pragma unroll
                for (int lo = 0; lo < 4; ++lo) {
                    u64 A[4] = { a[lo], a[4 | lo], a[8 | lo], a[12 | lo] };
                    u64 S[4] = { swapp(A[0]), swapp(A[1]), swapp(A[2]), swapp(A[3]) };
                    a[lo]      = row4p(Pg +  0, Qg +  0, A, S);
                    a[4 | lo]  = row4p(Pg +  4, Qg +  4, A, S);
                    a[8 | lo]  = row4p(Pg +  8, Qg +  8, A, S);
                    a[12 | lo] = row4p(Pg + 12, Qg + 12, A, S);
                }
            }
            {   // gate on bits (1,0)  (pair 5)
                u64 Pg[16], Qg[16];
#pragma unroll
                for (int e = 0; e < 16; ++e){ Pg[e] = G4P[l][5][e]; Qg[e] = G4Q[l][5][e]; }
#pragma unroll
                for (int hi = 0; hi < 4; ++hi) {
                    u64 A[4] = { a[hi*4], a[hi*4+1], a[hi*4+2], a[hi*4+3] };
                    u64 S[4] = { swapp(A[0]), swapp(A[1]), swapp(A[2]), swapp(A[3]) };
                    a[hi*4+0] = row4p(Pg +  0, Qg +  0, A, S);
                    a[hi*4+1] = row4p(Pg +  4, Qg +  4, A, S);
                    a[hi*4+2] = row4p(Pg +  8, Qg +  8, A, S);
                    a[hi*4+3] = row4p(Pg + 12, Qg + 12, A, S);
                }
            }
#pragma unroll
            for (int c = 0; c < 16; ++c)
                *reinterpret_cast<u64*>(&st[base | (c ^ sx4)]) = a[c];
        }
        __syncthreads();

        if (l == 0) {   // explicit CNOT-ring perm between layer 1 and layer 2
            u64 tmp[16];
#pragma unroll
            for (int r = 0; r < 16; ++r)
                tmp[r] = *reinterpret_cast<const u64*>(&st[swz(perm_src(tid + 256 * r))]);
            __syncthreads();
#pragma unroll
            for (int r = 0; r < 16; ++r)
                *reinterpret_cast<u64*>(&st[swz(tid + 256 * r)]) = tmp[r];
            __syncthreads();
        }
    }

    // ---- probabilities, with layer-2 CNOT-ring perm fused into the read ----
    float* orow = out + (size_t)b * (NGEN * DIMN) + (size_t)g * DIMN;
#pragma unroll
    for (int r = 0; r < 16; ++r) {
        const int i = tid + 256 * r;
        float2 a = st[swz(perm_src(i))];
        orow[i] = fmaf(a.x, a.x, a.y * a.y);
    }
}

// ---------------- linear layer: (x @ W^T + b) * 5, tiled for weight reuse ----------------
// grid: (DIMN/256, BATCH/64). Each CTA: 256 d-columns x 64 batch rows.
#define LB 64
__global__ void __launch_bounds__(256)
linear_kernel(const float* __restrict__ x,
              const float* __restrict__ lw,
              const float* __restrict__ lb,
              float* __restrict__ out)
{
    __shared__ float xs[LB][NQ];
    const int tid = threadIdx.x;
    const int d   = blockIdx.x * 256 + tid;
    const int b0  = blockIdx.y * LB;

    for (int t = tid; t < LB * NQ; t += 256)
        xs[t / NQ][t % NQ] = x[(b0 + t / NQ) * NQ + (t % NQ)];
    __syncthreads();

    const float4* wr = reinterpret_cast<const float4*>(lw + (size_t)d * NQ);
    const float4 w0 = wr[0], w1 = wr[1], w2 = wr[2];
    const float bias = lb[d];

#pragma unroll 4
    for (int bb = 0; bb < LB; ++bb) {
        const float* xr = xs[bb];
        float acc = bias;
        acc = fmaf(xr[0],  w0.x, acc); acc = fmaf(xr[1],  w0.y, acc);
        acc = fmaf(xr[2],  w0.z, acc); acc = fmaf(xr[3],  w0.w, acc);
        acc = fmaf(xr[4],  w1.x, acc); acc = fmaf(xr[5],  w1.y, acc);
        acc = fmaf(xr[6],  w1.z, acc); acc = fmaf(xr[7],  w1.w, acc);
        acc = fmaf(xr[8],  w2.x, acc); acc = fmaf(xr[9],  w2.y, acc);
        acc = fmaf(xr[10], w2.z, acc); acc = fmaf(xr[11], w2.w, acc);
        out[(size_t)(b0 + bb) * DIMN + d] = acc * 5.0f;
    }
}

extern "C" void kernel_launch(void* const* d_in, const int* in_sizes, int n_in,
                              void* d_out, int out_size)
{
    const float* x  = (const float*)d_in[0];   // (4096, 12)
    const float* qp = (const float*)d_in[1];   // (2, 108)
    const float* lw = (const float*)d_in[2];   // (4096, 12)
    const float* lb = (const float*)d_in[3];   // (4096,)
    float* out = (float*)d_out;                // probs (4096,8192) then converted_x (4096,4096)

    dim3 grid(4096, NGEN);
    qsim_kernel<<<grid, 256>>>(x, qp, out);
    dim3 lgrid(DIMN / 256, 4096 / LB);
    linear_kernel<<<lgrid, 256>>>(x, lw, lb, out + (size_t)4096 * (NGEN * DIMN));
}

// round 7
// speedup vs baseline: 1.5403x; 1.2234x over previous
#include <cuda_runtime.h>

#define NQ    12
#define DIMN  4096
#define NGEN  2

typedef unsigned long long u64;

// ---------------- packed f32x2 helpers ----------------
__device__ __forceinline__ u64 pk(float lo, float hi){
    u64 r; asm("mov.b64 %0, {%1, %2};" : "=l"(r) : "f"(lo), "f"(hi)); return r;
}
__device__ __forceinline__ void upk(u64 v, float& lo, float& hi){
    asm("mov.b64 {%0, %1}, %2;" : "=f"(lo), "=f"(hi) : "l"(v));
}
__device__ __forceinline__ u64 f2mul(u64 a, u64 b){
    u64 d; asm("mul.rn.f32x2 %0, %1, %2;" : "=l"(d) : "l"(a), "l"(b)); return d;
}
__device__ __forceinline__ u64 f2fma(u64 a, u64 b, u64 c){
    u64 d; asm("fma.rn.f32x2 %0, %1, %2, %3;" : "=l"(d) : "l"(a), "l"(b), "l"(c)); return d;
}
__device__ __forceinline__ u64 swapp(u64 v){          // (x,y) -> (y,x)
    float lo, hi; upk(v, lo, hi); return pk(hi, lo);
}

// scalar complex helper (setup phases only)
__device__ __forceinline__ float2 cmul(float2 a, float2 b){
    return make_float2(fmaf(a.x, b.x, -(a.y * b.y)), fmaf(a.x, b.y, a.y * b.x));
}

// CNOT ring permutation, closed form:
// j0 = i ^ ((i&1)<<11); out = j0 ^ (j0>>1)
__device__ __forceinline__ int perm_src(int i){
    int j0 = i ^ ((i & 1) << 11);
    return j0 ^ (j0 >> 1);
}

// bank-conflict swizzle for the state array
__device__ __forceinline__ int swz(int i){ return i ^ ((i >> 4) & 15); }

__device__ __forceinline__ u64 ld64(const float2* p){ return *reinterpret_cast<const u64*>(p); }
__device__ __forceinline__ void st64(float2* p, u64 v){ *reinterpret_cast<u64*>(p) = v; }

// packed row of a 4x4 complex gate: n = sum_k P[k](.)A[k] + Q[k](.)S[k]
__device__ __forceinline__ u64 row4p(const u64* __restrict__ P, const u64* __restrict__ Q,
                                     const u64* __restrict__ A, const u64* __restrict__ S){
    u64 n = f2mul(P[0], A[0]);
    n = f2fma(Q[0], S[0], n);
    n = f2fma(P[1], A[1], n);
    n = f2fma(Q[1], S[1], n);
    n = f2fma(P[2], A[2], n);
    n = f2fma(Q[2], S[2], n);
    n = f2fma(P[3], A[3], n);
    n = f2fma(Q[3], S[3], n);
    return n;
}

__device__ __forceinline__ void apply4(u64* a, int i0, int i1, int i2, int i3,
                                       const u64* Pg, const u64* Qg){
    u64 A[4] = { a[i0], a[i1], a[i2], a[i3] };
    u64 S[4] = { swapp(A[0]), swapp(A[1]), swapp(A[2]), swapp(A[3]) };
    a[i0] = row4p(Pg +  0, Qg +  0, A, S);
    a[i1] = row4p(Pg +  4, Qg +  4, A, S);
    a[i2] = row4p(Pg +  8, Qg +  8, A, S);
    a[i3] = row4p(Pg + 12, Qg + 12, A, S);
}
// gate along the 4-stride axis of the 16-amp register block
__device__ __forceinline__ void gate_q(u64* a, const u64* Pg, const u64* Qg){
#pragma unroll
    for (int r = 0; r < 4; ++r) apply4(a, r, 4 | r, 8 | r, 12 | r, Pg, Qg);
}
// gate along the 1-stride axis
__device__ __forceinline__ void gate_r(u64* a, const u64* Pg, const u64* Qg){
#pragma unroll
    for (int q = 0; q < 4; ++q) apply4(a, q*4, q*4 + 1, q*4 + 2, q*4 + 3, Pg, Qg);
}
__device__ __forceinline__ void ldgate(u64* Pg, u64* Qg,
                                       const u64* __restrict__ gp, const u64* __restrict__ gq){
#pragma unroll
    for (int e = 0; e < 16; ++e){ Pg[e] = gp[e]; Qg[e] = gq[e]; }
}

// ---------------- quantum circuit kernel ----------------
// grid: (4096 batch, 2 gen), block: 256 threads. State (4096 complex) in SMEM.
__global__ void __launch_bounds__(256, 2)
qsim_kernel(const float* __restrict__ x,
            const float* __restrict__ qp,
            float* __restrict__ out)
{
    __shared__ float2 st[4096];        // statevector (swizzled layout)
    __shared__ float2 Mg[2][12][4];    // fused RY*RX*RZ for layers 1,2
    __shared__ u64 G4P[2][6][16];      // (gx,gx) pairs of 4x4 gates
    __shared__ u64 G4Q[2][6][16];      // (-gy,gy) pairs of 4x4 gates
    __shared__ float2 v[12][2];        // layer-0 column vectors (per-sample)
    __shared__ float2 lowtab[16];      // product over wires 8..11
    __shared__ float2 hitab[256];      // product over wires 0..7

    const int tid = threadIdx.x;
    const int b   = blockIdx.x;
    const int g   = blockIdx.y;
    const float* w = qp + g * (3 * NQ * 3);

    // ---- phase 1: fused single-qubit gates (threads 0..35) ----
    if (tid < 36) {
        const int l = tid / 12, q = tid % 12;
        const float* wp = w + l * 36 + q * 3;
        float s1, c1, s2, c2, s3, c3;
        sincosf(0.5f * wp[0], &s1, &c1);
        sincosf(0.5f * wp[1], &s2, &c2);
        sincosf(0.5f * wp[2], &s3, &c3);
        float2 A00 = make_float2( c2 * c1, -c2 * s1);
        float2 A01 = make_float2( s2 * s1, -s2 * c1);
        float2 A10 = make_float2(-s2 * s1, -s2 * c1);
        float2 A11 = make_float2( c2 * c1,  c2 * s1);
        float2 M00 = make_float2(c3*A00.x - s3*A10.x, c3*A00.y - s3*A10.y);
        float2 M01 = make_float2(c3*A01.x - s3*A11.x, c3*A01.y - s3*A11.y);
        float2 M10 = make_float2(s3*A00.x + c3*A10.x, s3*A00.y + c3*A10.y);
        float2 M11 = make_float2(s3*A01.x + c3*A11.x, s3*A01.y + c3*A11.y);
        if (l == 0) {
            float sx, cx;
            sincosf(0.5f * x[b * NQ + q], &sx, &cx);
            v[q][0] = make_float2(M00.x*cx + M01.x*sx, M00.y*cx + M01.y*sx);
            v[q][1] = make_float2(M10.x*cx + M11.x*sx, M10.y*cx + M11.y*sx);
        } else {
            Mg[l-1][q][0] = M00; Mg[l-1][q][1] = M01;
            Mg[l-1][q][2] = M10; Mg[l-1][q][3] = M11;
        }
    }
    __syncthreads();

    // ---- phase 2: packed 4x4 kron gates, low/high product tables ----
    if (tid < 192) {
        const int l = tid / 96, u = tid % 96, pr = u / 16, e = u % 16;
        const int r = e >> 2, c = e & 3;
        float2 gm = cmul(Mg[l][2*pr    ][(r >> 1) * 2 + (c >> 1)],
                         Mg[l][2*pr + 1][(r &  1) * 2 + (c &  1)]);
        G4P[l][pr][e] = pk(gm.x, gm.x);
        G4Q[l][pr][e] = pk(-gm.y, gm.y);
    } else if (tid < 208) {
        const int idx = tid - 192;
        lowtab[idx] = cmul(cmul(v[8][(idx >> 3) & 1], v[ 9][(idx >> 2) & 1]),
                           cmul(v[10][(idx >> 1) & 1], v[11][ idx       & 1]));
    }
    {
        float2 hv = v[0][(tid >> 7) & 1];
#pragma unroll
        for (int y = 1; y < 8; ++y)
            hv = cmul(hv, v[y][(tid >> (7 - y)) & 1]);
        hitab[tid] = hv;
    }
    __syncthreads();

    // ---- layers: 3 SMEM round-trips per layer, 2 gates per round ----
#pragma unroll
    for (int l = 0; l < 2; ++l) {
        // ===== round A: bit-pairs (11,10) & (9,8); pairs 0 and 1 =====
        {
            u64 a[16];
            if (l == 0) {
                // init fused: product state with layer-0 CNOT-ring perm
#pragma unroll
                for (int q = 0; q < 4; ++q)
#pragma unroll
                for (int r = 0; r < 4; ++r) {
                    const int idx = tid + (q << 10) + (r << 8);
                    const int j = perm_src(idx);
                    float2 val = cmul(hitab[j >> 4], lowtab[j & 15]);
                    a[q*4 + r] = pk(val.x, val.y);
                }
            } else {
                // gather with mid-circuit CNOT-ring perm fused into the load
#pragma unroll
                for (int q = 0; q < 4; ++q)
#pragma unroll
                for (int r = 0; r < 4; ++r) {
                    const int idx = tid + (q << 10) + (r << 8);
                    a[q*4 + r] = ld64(&st[swz(perm_src(idx))]);
                }
                __syncthreads();   // all gathers done before any store below
            }
            u64 Pg[16], Qg[16];
            ldgate(Pg, Qg, &G4P[l][0][0], &G4Q[l][0][0]);
            gate_q(a, Pg, Qg);
            ldgate(Pg, Qg, &G4P[l][1][0], &G4Q[l][1][0]);
            gate_r(a, Pg, Qg);
#pragma unroll
            for (int q = 0; q < 4; ++q)
#pragma unroll
            for (int r = 0; r < 4; ++r)
                st64(&st[swz(tid + (q << 10) + (r << 8))], a[q*4 + r]);
        }
        __syncthreads();

        // ===== round B: bit-pairs (7,6) & (5,4); pairs 2 and 3 =====
        {
            const int base = ((tid >> 4) << 8) | (tid & 15);
            u64 a[16];
#pragma unroll
            for (int q = 0; q < 4; ++q)
#pragma unroll
            for (int r = 0; r < 4; ++r)
                a[q*4 + r] = ld64(&st[swz(base + (q << 6) + (r << 4))]);
            u64 Pg[16], Qg[16];
            ldgate(Pg, Qg, &G4P[l][2][0], &G4Q[l][2][0]);
            gate_q(a, Pg, Qg);
            ldgate(Pg, Qg, &G4P[l][3][0], &G4Q[l][3][0]);
            gate_r(a, Pg, Qg);
#pragma unroll
            for (int q = 0; q < 4; ++q)
#pragma unroll
            for (int r = 0; r < 4; ++r)
                st64(&st[swz(base + (q << 6) + (r << 4))], a[q*4 + r]);
        }
        __syncthreads();

        // ===== round C: bit-pairs (3,2) & (1,0); pairs 4 and 5 =====
        {
            const int base = tid << 4;
            const int sx4  = tid & 15;
            u64 a[16];
#pragma unroll
            for (int c = 0; c < 16; ++c)
                a[c] = ld64(&st[base | (c ^ sx4)]);
            u64 Pg[16], Qg[16];
            ldgate(Pg, Qg, &G4P[l][4][0], &G4Q[l][4][0]);
            gate_q(a, Pg, Qg);
            ldgate(Pg, Qg, &G4P[l][5][0], &G4Q[l][5][0]);
            gate_r(a, Pg, Qg);
#pragma unroll
            for (int c = 0; c < 16; ++c)
                st64(&st[base | (c ^ sx4)], a[c]);
        }
        __syncthreads();
    }

    // ---- probabilities, with layer-2 CNOT-ring perm fused into the read ----
    float* orow = out + (size_t)b * (NGEN * DIMN) + (size_t)g * DIMN;
#pragma unroll
    for (int r = 0; r < 16; ++r) {
        const int i = tid + 256 * r;
        float2 a = st[swz(perm_src(i))];
        orow[i] = fmaf(a.x, a.x, a.y * a.y);
    }
}

// ---------------- linear layer: (x @ W^T + b) * 5, tiled; 2 cols/thread ----------------
#define LB 64
__global__ void __launch_bounds__(256)
linear_kernel(const float* __restrict__ x,
              const float* __restrict__ lw,
              const float* __restrict__ lb,
              float* __restrict__ out)
{
    __shared__ float xs[LB][NQ];
    const int tid = threadIdx.x;
    const int d   = blockIdx.x * 512 + tid * 2;
    const int b0  = blockIdx.y * LB;

    for (int t = tid; t < LB * NQ; t += 256)
        xs[t / NQ][t % NQ] = x[(b0 + t / NQ) * NQ + (t % NQ)];
    __syncthreads();

    const float4* wa = reinterpret_cast<const float4*>(lw + (size_t)d * NQ);
    const float4* wb = reinterpret_cast<const float4*>(lw + (size_t)(d + 1) * NQ);
    const float4 a0 = wa[0], a1 = wa[1], a2 = wa[2];
    const float4 c0 = wb[0], c1 = wb[1], c2 = wb[2];
    const float bias0 = lb[d], bias1 = lb[d + 1];

#pragma unroll 4
    for (int bb = 0; bb < LB; ++bb) {
        const float* xr = xs[bb];
        float s0 = bias0, s1 = bias1;
        s0 = fmaf(xr[0],  a0.x, s0); s1 = fmaf(xr[0],  c0.x, s1);
        s0 = fmaf(xr[1],  a0.y, s0); s1 = fmaf(xr[1],  c0.y, s1);
        s0 = fmaf(xr[2],  a0.z, s0); s1 = fmaf(xr[2],  c0.z, s1);
        s0 = fmaf(xr[3],  a0.w, s0); s1 = fmaf(xr[3],  c0.w, s1);
        s0 = fmaf(xr[4],  a1.x, s0); s1 = fmaf(xr[4],  c1.x, s1);
        s0 = fmaf(xr[5],  a1.y, s0); s1 = fmaf(xr[5],  c1.y, s1);
        s0 = fmaf(xr[6],  a1.z, s0); s1 = fmaf(xr[6],  c1.z, s1);
        s0 = fmaf(xr[7],  a1.w, s0); s1 = fmaf(xr[7],  c1.w, s1);
        s0 = fmaf(xr[8],  a2.x, s0); s1 = fmaf(xr[8],  c2.x, s1);
        s0 = fmaf(xr[9],  a2.y, s0); s1 = fmaf(xr[9],  c2.y, s1);
        s0 = fmaf(xr[10], a2.z, s0); s1 = fmaf(xr[10], c2.z, s1);
        s0 = fmaf(xr[11], a2.w, s0); s1 = fmaf(xr[11], c2.w, s1);
        float2 o = make_float2(s0 * 5.0f, s1 * 5.0f);
        *reinterpret_cast<float2*>(&out[(size_t)(b0 + bb) * DIMN + d]) = o;
    }
}

extern "C" void kernel_launch(void* const* d_in, const int* in_sizes, int n_in,
                              void* d_out, int out_size)
{
    const float* x  = (const float*)d_in[0];   // (4096, 12)
    const float* qp = (const float*)d_in[1];   // (2, 108)
    const float* lw = (const float*)d_in[2];   // (4096, 12)
    const float* lb = (const float*)d_in[3];   // (4096,)
    float* out = (float*)d_out;                // probs (4096,8192) then converted_x (4096,4096)

    dim3 grid(4096, NGEN);
    qsim_kernel<<<grid, 256>>>(x, qp, out);
    dim3 lgrid(DIMN / 512, 4096 / LB);
    linear_kernel<<<lgrid, 256>>>(x, lw, lb, out + (size_t)4096 * (NGEN * DIMN));
}

// round 8
// speedup vs baseline: 1.5578x; 1.0114x over previous
#include <cuda_runtime.h>

#define NQ    12
#define DIMN  4096
#define NGEN  2

typedef unsigned long long u64;

// ---------------- packed f32x2 helpers ----------------
__device__ __forceinline__ u64 pk(float lo, float hi){
    u64 r; asm("mov.b64 %0, {%1, %2};" : "=l"(r) : "f"(lo), "f"(hi)); return r;
}
__device__ __forceinline__ void upk(u64 v, float& lo, float& hi){
    asm("mov.b64 {%0, %1}, %2;" : "=f"(lo), "=f"(hi) : "l"(v));
}
__device__ __forceinline__ u64 f2mul(u64 a, u64 b){
    u64 d; asm("mul.rn.f32x2 %0, %1, %2;" : "=l"(d) : "l"(a), "l"(b)); return d;
}
__device__ __forceinline__ u64 f2fma(u64 a, u64 b, u64 c){
    u64 d; asm("fma.rn.f32x2 %0, %1, %2, %3;" : "=l"(d) : "l"(a), "l"(b), "l"(c)); return d;
}
__device__ __forceinline__ u64 swapp(u64 v){          // (x,y) -> (y,x)
    float lo, hi; upk(v, lo, hi); return pk(hi, lo);
}

// scalar complex helper (setup phases only)
__device__ __forceinline__ float2 cmul(float2 a, float2 b){
    return make_float2(fmaf(a.x, b.x, -(a.y * b.y)), fmaf(a.x, b.y, a.y * b.x));
}

// CNOT ring permutation, closed form:
// j0 = i ^ ((i&1)<<11); out = j0 ^ (j0>>1)
__device__ __forceinline__ int perm_src(int i){
    int j0 = i ^ ((i & 1) << 11);
    return j0 ^ (j0 >> 1);
}

// bank swizzle for the state array
__device__ __forceinline__ int swz(int i){ return i ^ ((i >> 4) & 15); }

__device__ __forceinline__ u64 ld64(const float2* p){ return *reinterpret_cast<const u64*>(p); }
__device__ __forceinline__ void st64(float2* p, u64 v){ *reinterpret_cast<u64*>(p) = v; }

// packed row of a 4x4 complex gate: n = sum_k P[k](.)A[k] + Q[k](.)S[k]
__device__ __forceinline__ u64 row4p(const u64* __restrict__ P, const u64* __restrict__ Q,
                                     const u64* __restrict__ A, const u64* __restrict__ S){
    u64 n = f2mul(P[0], A[0]);
    n = f2fma(Q[0], S[0], n);
    n = f2fma(P[1], A[1], n);
    n = f2fma(Q[1], S[1], n);
    n = f2fma(P[2], A[2], n);
    n = f2fma(Q[2], S[2], n);
    n = f2fma(P[3], A[3], n);
    n = f2fma(Q[3], S[3], n);
    return n;
}

__device__ __forceinline__ void apply4(u64* a, int i0, int i1, int i2, int i3,
                                       const u64* Pg, const u64* Qg){
    u64 A[4] = { a[i0], a[i1], a[i2], a[i3] };
    u64 S[4] = { swapp(A[0]), swapp(A[1]), swapp(A[2]), swapp(A[3]) };
    a[i0] = row4p(Pg +  0, Qg +  0, A, S);
    a[i1] = row4p(Pg +  4, Qg +  4, A, S);
    a[i2] = row4p(Pg +  8, Qg +  8, A, S);
    a[i3] = row4p(Pg + 12, Qg + 12, A, S);
}
// gate along the 4-stride axis of the 16-amp register block
__device__ __forceinline__ void gate_q(u64* a, const u64* Pg, const u64* Qg){
#pragma unroll
    for (int r = 0; r < 4; ++r) apply4(a, r, 4 | r, 8 | r, 12 | r, Pg, Qg);
}
// gate along the 1-stride axis
__device__ __forceinline__ void gate_r(u64* a, const u64* Pg, const u64* Qg){
#pragma unroll
    for (int q = 0; q < 4; ++q) apply4(a, q*4, q*4 + 1, q*4 + 2, q*4 + 3, Pg, Qg);
}
// broadcast gate load, vectorized to LDS.128
__device__ __forceinline__ void ldgate(u64* Pg, u64* Qg,
                                       const u64* __restrict__ gp, const u64* __restrict__ gq){
#pragma unroll
    for (int e = 0; e < 16; e += 2){
        ulonglong2 p = *reinterpret_cast<const ulonglong2*>(gp + e);
        ulonglong2 q = *reinterpret_cast<const ulonglong2*>(gq + e);
        Pg[e] = p.x; Pg[e+1] = p.y;
        Qg[e] = q.x; Qg[e+1] = q.y;
    }
}

// ---------------- quantum circuit kernel ----------------
// grid: (4096 batch, 2 gen), block: 256 threads. State (4096 complex) in SMEM.
__global__ void __launch_bounds__(256, 2)
qsim_kernel(const float* __restrict__ x,
            const float* __restrict__ qp,
            float* __restrict__ out)
{
    __shared__ float2 st[4096];        // statevector (swizzled layout)
    __shared__ float2 Mg[2][12][4];    // fused RY*RX*RZ for layers 1,2
    __shared__ __align__(16) u64 G4P[2][6][16];  // (gx,gx) pairs of 4x4 gates
    __shared__ __align__(16) u64 G4Q[2][6][16];  // (-gy,gy) pairs of 4x4 gates
    __shared__ float2 v[12][2];        // layer-0 column vectors (per-sample)
    __shared__ float2 lowtab[16];      // product over wires 8..11
    __shared__ float2 hitab[256];      // product over wires 0..7

    const int tid = threadIdx.x;
    const int b   = blockIdx.x;
    const int g   = blockIdx.y;
    const float* w = qp + g * (3 * NQ * 3);

    // ---- phase 1: fused single-qubit gates (threads 0..35) ----
    if (tid < 36) {
        const int l = tid / 12, q = tid % 12;
        const float* wp = w + l * 36 + q * 3;
        float s1, c1, s2, c2, s3, c3;
        sincosf(0.5f * wp[0], &s1, &c1);
        sincosf(0.5f * wp[1], &s2, &c2);
        sincosf(0.5f * wp[2], &s3, &c3);
        float2 A00 = make_float2( c2 * c1, -c2 * s1);
        float2 A01 = make_float2( s2 * s1, -s2 * c1);
        float2 A10 = make_float2(-s2 * s1, -s2 * c1);
        float2 A11 = make_float2( c2 * c1,  c2 * s1);
        float2 M00 = make_float2(c3*A00.x - s3*A10.x, c3*A00.y - s3*A10.y);
        float2 M01 = make_float2(c3*A01.x - s3*A11.x, c3*A01.y - s3*A11.y);
        float2 M10 = make_float2(s3*A00.x + c3*A10.x, s3*A00.y + c3*A10.y);
        float2 M11 = make_float2(s3*A01.x + c3*A11.x, s3*A01.y + c3*A11.y);
        if (l == 0) {
            float sx, cx;
            sincosf(0.5f * x[b * NQ + q], &sx, &cx);
            v[q][0] = make_float2(M00.x*cx + M01.x*sx, M00.y*cx + M01.y*sx);
            v[q][1] = make_float2(M10.x*cx + M11.x*sx, M10.y*cx + M11.y*sx);
        } else {
            Mg[l-1][q][0] = M00; Mg[l-1][q][1] = M01;
            Mg[l-1][q][2] = M10; Mg[l-1][q][3] = M11;
        }
    }
    __syncthreads();

    // ---- phase 2: packed 4x4 kron gates, low/high product tables ----
    if (tid < 192) {
        const int l = tid / 96, u = tid % 96, pr = u / 16, e = u % 16;
        const int r = e >> 2, c = e & 3;
        float2 gm = cmul(Mg[l][2*pr    ][(r >> 1) * 2 + (c >> 1)],
                         Mg[l][2*pr + 1][(r &  1) * 2 + (c &  1)]);
        G4P[l][pr][e] = pk(gm.x, gm.x);
        G4Q[l][pr][e] = pk(-gm.y, gm.y);
    } else if (tid < 208) {
        const int idx = tid - 192;
        lowtab[idx] = cmul(cmul(v[8][(idx >> 3) & 1], v[ 9][(idx >> 2) & 1]),
                           cmul(v[10][(idx >> 1) & 1], v[11][ idx       & 1]));
    }
    {
        float2 hv = v[0][(tid >> 7) & 1];
#pragma unroll
        for (int y = 1; y < 8; ++y)
            hv = cmul(hv, v[y][(tid >> (7 - y)) & 1]);
        hitab[tid] = hv;
    }
    __syncthreads();

    // ---- layers: 3 SMEM round-trips per layer, 2 gates per round ----
#pragma unroll
    for (int l = 0; l < 2; ++l) {
        // ===== round A: bit-pairs (11,10) & (9,8); pairs 0 and 1 (cross-warp) =====
        {
            u64 a[16];
            u64 Pg[16], Qg[16];
            if (l == 0) {
                // init fused: product state with layer-0 CNOT-ring perm
#pragma unroll
                for (int q = 0; q < 4; ++q)
#pragma unroll
                for (int r = 0; r < 4; ++r) {
                    const int idx = tid + (q << 10) + (r << 8);
                    const int j = perm_src(idx);
                    float2 val = cmul(hitab[j >> 4], lowtab[j & 15]);
                    a[q*4 + r] = pk(val.x, val.y);
                }
                ldgate(Pg, Qg, &G4P[l][0][0], &G4Q[l][0][0]);
                gate_q(a, Pg, Qg);
                ldgate(Pg, Qg, &G4P[l][1][0], &G4Q[l][1][0]);
                gate_r(a, Pg, Qg);
            } else {
                // gather with mid-circuit CNOT-ring perm fused into the load;
                // compute gates BEFORE the barrier so warps arrive late together
#pragma unroll
                for (int q = 0; q < 4; ++q)
#pragma unroll
                for (int r = 0; r < 4; ++r) {
                    const int idx = tid + (q << 10) + (r << 8);
                    a[q*4 + r] = ld64(&st[swz(perm_src(idx))]);
                }
                ldgate(Pg, Qg, &G4P[l][0][0], &G4Q[l][0][0]);
                gate_q(a, Pg, Qg);
                ldgate(Pg, Qg, &G4P[l][1][0], &G4Q[l][1][0]);
                gate_r(a, Pg, Qg);
                __syncthreads();   // all gathers done before any store below
            }
#pragma unroll
            for (int q = 0; q < 4; ++q)
#pragma unroll
            for (int r = 0; r < 4; ++r)
                st64(&st[swz(tid + (q << 10) + (r << 8))], a[q*4 + r]);
        }
        __syncthreads();           // round A stores visible to all warps

        // ===== round B: bit-pairs (7,6) & (5,4); warp-private slab =====
        {
            const int base = ((tid >> 4) << 8) | (tid & 15);
            u64 a[16];
#pragma unroll
            for (int q = 0; q < 4; ++q)
#pragma unroll
            for (int r = 0; r < 4; ++r)
                a[q*4 + r] = ld64(&st[swz(base + (q << 6) + (r << 4))]);
            u64 Pg[16], Qg[16];
            ldgate(Pg, Qg, &G4P[l][2][0], &G4Q[l][2][0]);
            gate_q(a, Pg, Qg);
            ldgate(Pg, Qg, &G4P[l][3][0], &G4Q[l][3][0]);
            gate_r(a, Pg, Qg);
#pragma unroll
            for (int q = 0; q < 4; ++q)
#pragma unroll
            for (int r = 0; r < 4; ++r)
                st64(&st[swz(base + (q << 6) + (r << 4))], a[q*4 + r]);
        }
        __syncwarp();              // B->C dependency is within-warp only

        // ===== round C: bit-pairs (3,2) & (1,0); warp-private slab =====
        {
            const int base = tid << 4;
            const int sx4  = tid & 15;
            u64 a[16];
#pragma unroll
            for (int c = 0; c < 16; ++c)
                a[c] = ld64(&st[base | (c ^ sx4)]);
            u64 Pg[16], Qg[16];
            ldgate(Pg, Qg, &G4P[l][4][0], &G4Q[l][4][0]);
            gate_q(a, Pg, Qg);
            ldgate(Pg, Qg, &G4P[l][5][0], &G4Q[l][5][0]);
            gate_r(a, Pg, Qg);
#pragma unroll
            for (int c = 0; c < 16; ++c)
                st64(&st[base | (c ^ sx4)], a[c]);
        }
        __syncthreads();           // cross-warp gather/readout follows
    }

    // ---- probabilities, with layer-2 CNOT-ring perm fused into the read ----
    float* orow = out + (size_t)b * (NGEN * DIMN) + (size_t)g * DIMN;
#pragma unroll
    for (int r = 0; r < 16; ++r) {
        const int i = tid + 256 * r;
        float2 a = st[swz(perm_src(i))];
        orow[i] = fmaf(a.x, a.x, a.y * a.y);
    }
}

// ---------------- linear layer: (x @ W^T + b) * 5, tiled; 4 cols/thread ----------------
#define LB 64
__global__ void __launch_bounds__(256)
linear_kernel(const float* __restrict__ x,
              const float* __restrict__ lw,
              const float* __restrict__ lb,
              float* __restrict__ out)
{
    __shared__ float4 xs4[LB][3];
    const int tid = threadIdx.x;
    const int d   = blockIdx.x * 1024 + tid * 4;
    const int b0  = blockIdx.y * LB;

    // x rows are 12 floats = 3 float4, 16B-aligned (48B rows)
    const float4* xsrc = reinterpret_cast<const float4*>(x + (size_t)b0 * NQ);
    for (int t = tid; t < LB * 3; t += 256)
        xs4[t / 3][t % 3] = xsrc[t];
    __syncthreads();

    // weights & bias for 4 columns, pre-scaled by TEMPERATURE=5
    float wr[4][12];
    float bias[4];
#pragma unroll
    for (int c = 0; c < 4; ++c) {
        const float4* wp = reinterpret_cast<const float4*>(lw + (size_t)(d + c) * NQ);
#pragma unroll
        for (int j = 0; j < 3; ++j) {
            float4 wv = wp[j];
            wr[c][j*4+0] = wv.x * 5.0f; wr[c][j*4+1] = wv.y * 5.0f;
            wr[c][j*4+2] = wv.z * 5.0f; wr[c][j*4+3] = wv.w * 5.0f;
        }
        bias[c] = lb[d + c] * 5.0f;
    }

#pragma unroll 2
    for (int bb = 0; bb < LB; ++bb) {
        float4 x0 = xs4[bb][0], x1 = xs4[bb][1], x2 = xs4[bb][2];
        float xl[12] = { x0.x, x0.y, x0.z, x0.w, x1.x, x1.y, x1.z, x1.w,
                         x2.x, x2.y, x2.z, x2.w };
        float4 o;
        float* op = &o.x;
#pragma unroll
        for (int c = 0; c < 4; ++c) {
            float acc = bias[c];
#pragma unroll
            for (int j = 0; j < 12; ++j) acc = fmaf(xl[j], wr[c][j], acc);
            op[c] = acc;
        }
        *reinterpret_cast<float4*>(&out[(size_t)(b0 + bb) * DIMN + d]) = o;
    }
}

extern "C" void kernel_launch(void* const* d_in, const int* in_sizes, int n_in,
                              void* d_out, int out_size)
{
    const float* x  = (const float*)d_in[0];   // (4096, 12)
    const float* qp = (const float*)d_in[1];   // (2, 108)
    const float* lw = (const float*)d_in[2];   // (4096, 12)
    const float* lb = (const float*)d_in[3];   // (4096,)
    float* out = (float*)d_out;                // probs (4096,8192) then converted_x (4096,4096)

    dim3 grid(4096, NGEN);
    qsim_kernel<<<grid, 256>>>(x, qp, out);
    dim3 lgrid(DIMN / 1024, 4096 / LB);
    linear_kernel<<<lgrid, 256>>>(x, lw, lb, out + (size_t)4096 * (NGEN * DIMN));
}